// round 13
// baseline (speedup 1.0000x reference)
#include <cuda_runtime.h>
#include <cuda_fp16.h>
#include <cstdint>
#include <cstddef>

// Problem shape (fixed by the dataset)
#define BT   8192
#define IN_F 4096
#define OUT_F 4096
#define NEXP 8
#define RLOR 16
#define ERC  128
#define KSPLIT 4

// GEMM tiling (fp16 operands, fp32 accum) — R7 champion config
#define BM 128
#define BN 128
#define BKT 64                        // K halves per chunk = 128B rows
#define NSTAGE 3
#define PADH 72                       // smem row stride in halves (144B)
#define TILE_B (BM * PADH * 2)        // 18432 B per tile
#define STAGE_B (2 * TILE_B)          // 36864 B per stage
#define SMEM_BYTES (NSTAGE * STAGE_B) // 110592 B

// Scratch (no device allocation allowed -> __device__ globals)
__device__ __half g_xh [(size_t)BT * IN_F];         // 64 MB: x in fp16
__device__ __half g_wbh[(size_t)OUT_F * IN_F];      // 32 MB: W_base in fp16
__device__ __half g_awh[(size_t)ERC * IN_F];        // 1 MB:  A_all in fp16
__device__ __half g_ballh[(size_t)OUT_F * ERC];     // 1 MB:  B_all repacked fp16
__device__ float  g_si [(size_t)KSPLIT * BT * ERC]; // 16 MB: split-K fp32 partials
__device__ __half g_sih[(size_t)BT * ERC];          // 2 MB:  scaled si in fp16
__device__ float  g_wfull[(size_t)BT * NEXP];       // 256 KB: per-token expert weights

__device__ __forceinline__ uint32_t smem_u32(const void* p) {
    uint32_t a;
    asm("{ .reg .u64 t; cvta.to.shared.u64 t, %1; cvt.u32.u64 %0, t; }" : "=r"(a) : "l"(p));
    return a;
}
__device__ __forceinline__ void cpa16(uint32_t dst, const void* src) {
    asm volatile("cp.async.cg.shared.global [%0], [%1], 16;" :: "r"(dst), "l"(src));
}
#define CPA_COMMIT() asm volatile("cp.async.commit_group;" ::: "memory")
#define CPA_WAIT(n)  asm volatile("cp.async.wait_group %0;" :: "n"(n) : "memory")

__device__ __forceinline__ void ldsm_x4(uint32_t& r0, uint32_t& r1,
                                        uint32_t& r2, uint32_t& r3, uint32_t addr) {
    asm volatile("ldmatrix.sync.aligned.m8n8.x4.shared.b16 {%0,%1,%2,%3}, [%4];"
                 : "=r"(r0), "=r"(r1), "=r"(r2), "=r"(r3) : "r"(addr));
}

__device__ __forceinline__ void mma_f16(float c[4],
                                        uint32_t a0, uint32_t a1, uint32_t a2, uint32_t a3,
                                        uint32_t b0, uint32_t b1) {
    asm volatile(
        "mma.sync.aligned.m16n8k16.row.col.f32.f16.f16.f32 "
        "{%0,%1,%2,%3}, {%4,%5,%6,%7}, {%8,%9}, {%0,%1,%2,%3};"
        : "+f"(c[0]), "+f"(c[1]), "+f"(c[2]), "+f"(c[3])
        : "r"(a0), "r"(a1), "r"(a2), "r"(a3), "r"(b0), "r"(b1));
}

// ---------------------------------------------------------------------------
// Dual-phase FP16 GEMM (cp.async 3-stage, ldmatrix fragments) — R7 config.
//   C = A0 @ B0^T (K0) + A1 @ B1^T (K1) + bias   (fp32 accumulate/output)
// A row-major [M][lda], B row-major [N][ldb], lda/ldb in halves.
// blockIdx.z = split-K slice (offsets A0/B0 by z*K0 along K, C by z*cpart).
// ---------------------------------------------------------------------------
__global__ __launch_bounds__(256, 2)
void gemm_f16_kernel(const __half* __restrict__ A0, int lda0,
                     const __half* __restrict__ B0, int ldb0, int K0,
                     const __half* __restrict__ A1, int lda1,
                     const __half* __restrict__ B1, int ldb1, int K1,
                     float* __restrict__ C, int ldc,
                     const float* __restrict__ bias,
                     size_t cpart)
{
    extern __shared__ char smem_raw[];

    const int z = blockIdx.z;
    A0 += (size_t)z * K0;
    B0 += (size_t)z * K0;
    C  += (size_t)z * cpart;

    const int tid  = threadIdx.x;
    const int bm   = blockIdx.y * BM;
    const int bn   = blockIdx.x * BN;
    const int warp = tid >> 5;
    const int lane = tid & 31;
    const int wm   = (warp >> 2) * 64;   // 2 warps along M
    const int wn   = (warp & 3) * 32;    // 4 warps along N
    const int g    = lane >> 2;
    const int t4   = lane & 3;

    float acc[4][4][4];
    #pragma unroll
    for (int i = 0; i < 4; i++)
        #pragma unroll
        for (int j = 0; j < 4; j++)
            #pragma unroll
            for (int v = 0; v < 4; v++) acc[i][j][v] = 0.f;

    // Loader: 4 slabs of 32 rows; 8 threads x 16B (8 halves) across a 64-half row
    const int l_row  = tid >> 3;           // 0..31
    const int l_colh = (tid & 7) * 8;      // 0..56 halves

    const uint32_t smem_base = smem_u32(smem_raw);
    const uint32_t wA0 = smem_base + (l_row * PADH + l_colh) * 2;
    const uint32_t wB0 = wA0 + TILE_B;

    // ldmatrix per-thread row/col selectors
    const int lm_a_row = lane & 15;
    const int lm_a_k8  = (lane >> 4) * 8;
    const int lm_b_row = ((lane >> 4) & 1) * 8 + (lane & 7);
    const int lm_b_k8  = ((lane >> 3) & 1) * 8;

    const int T0 = K0 / BKT;
    const int T1 = K1 / BKT;
    const int T  = T0 + T1;

    auto load_chunk = [&](int c) {
        const uint32_t st = (uint32_t)(c % NSTAGE) * STAGE_B;
        const __half *A, *B; int lda, ldb, k0;
        if (c < T0) { A = A0; lda = lda0; B = B0; ldb = ldb0; k0 = c * BKT; }
        else        { A = A1; lda = lda1; B = B1; ldb = ldb1; k0 = (c - T0) * BKT; }
        const __half* ap = A + (size_t)(bm + l_row) * lda + k0 + l_colh;
        const __half* bp = B + (size_t)(bn + l_row) * ldb + k0 + l_colh;
        #pragma unroll
        for (int i = 0; i < 4; i++) {
            cpa16(st + wA0 + i * (32 * PADH * 2), ap + (size_t)(i * 32) * lda);
            cpa16(st + wB0 + i * (32 * PADH * 2), bp + (size_t)(i * 32) * ldb);
        }
    };

    auto compute = [&](int buf) {
        const uint32_t aB = smem_base + (uint32_t)buf * STAGE_B;
        const uint32_t bB = aB + TILE_B;
        #pragma unroll
        for (int ks = 0; ks < 4; ks++) {          // each ks = one k16 step
            const int kh = ks * 16;                // half offset
            uint32_t af[4][4], bf[4][2];
            #pragma unroll
            for (int mt = 0; mt < 4; mt++) {
                const uint32_t ad = aB +
                    ((wm + mt * 16 + lm_a_row) * PADH + kh + lm_a_k8) * 2;
                ldsm_x4(af[mt][0], af[mt][1], af[mt][2], af[mt][3], ad);
            }
            #pragma unroll
            for (int pr = 0; pr < 2; pr++) {
                const uint32_t bd = bB +
                    ((wn + pr * 16 + lm_b_row) * PADH + kh + lm_b_k8) * 2;
                ldsm_x4(bf[2 * pr][0], bf[2 * pr][1],
                        bf[2 * pr + 1][0], bf[2 * pr + 1][1], bd);
            }
            #pragma unroll
            for (int mt = 0; mt < 4; mt++)
                #pragma unroll
                for (int nt = 0; nt < 4; nt++)
                    mma_f16(acc[mt][nt], af[mt][0], af[mt][1], af[mt][2], af[mt][3],
                            bf[nt][0], bf[nt][1]);
        }
    };

    // prologue: stages 0..NSTAGE-2
    #pragma unroll
    for (int p = 0; p < NSTAGE - 1; p++) {
        if (p < T) load_chunk(p);
        CPA_COMMIT();
    }

    for (int t = 0; t < T; t++) {
        CPA_WAIT(NSTAGE - 2);       // chunk t landed
        __syncthreads();            // visibility + stage reuse guard
        if (t + NSTAGE - 1 < T) load_chunk(t + NSTAGE - 1);
        CPA_COMMIT();
        compute(t % NSTAGE);
    }

    // Epilogue (fp32)
    #pragma unroll
    for (int mt = 0; mt < 4; mt++) {
        #pragma unroll
        for (int nt = 0; nt < 4; nt++) {
            const int row0 = bm + wm + mt * 16 + g;
            const int col0 = bn + wn + nt * 8 + t4 * 2;
            float bv0 = 0.f, bv1 = 0.f;
            if (bias) { bv0 = bias[col0]; bv1 = bias[col0 + 1]; }
            float2 o0 = make_float2(acc[mt][nt][0] + bv0, acc[mt][nt][1] + bv1);
            float2 o1 = make_float2(acc[mt][nt][2] + bv0, acc[mt][nt][3] + bv1);
            *(float2*)(C + (size_t)row0 * ldc + col0)       = o0;
            *(float2*)(C + (size_t)(row0 + 8) * ldc + col0) = o1;
        }
    }
}

// ---------------------------------------------------------------------------
// Fused router + x conversion. One warp per token:
//  - single pass over fp32 x row: accumulate 8 router dots (exact fp32)
//    AND write the fp16 row of g_xh.
//  - top-2 + softmax -> dense per-token expert weight vector g_wfull[tok][e].
// ---------------------------------------------------------------------------
__global__ void router_conv_kernel(const float* __restrict__ x,
                                   const float* __restrict__ Wr)
{
    const int tok  = (blockIdx.x * blockDim.x + threadIdx.x) >> 5;
    const int lane = threadIdx.x & 31;
    if (tok >= BT) return;

    const float* xr = x + (size_t)tok * IN_F;
    __half* xo = g_xh + (size_t)tok * IN_F;
    float acc[NEXP];
    #pragma unroll
    for (int e = 0; e < NEXP; e++) acc[e] = 0.f;

    for (int k = lane * 4; k < IN_F; k += 128) {
        float4 xv = *(const float4*)(xr + k);
        // fused fp16 conversion write (8B per lane)
        __half2 hh[2];
        hh[0] = __float22half2_rn(make_float2(xv.x, xv.y));
        hh[1] = __float22half2_rn(make_float2(xv.z, xv.w));
        *(uint2*)(xo + k) = *(const uint2*)hh;
        #pragma unroll
        for (int e = 0; e < NEXP; e++) {
            float4 wv = *(const float4*)(Wr + (size_t)e * IN_F + k);
            acc[e] += xv.x * wv.x + xv.y * wv.y + xv.z * wv.z + xv.w * wv.w;
        }
    }
    #pragma unroll
    for (int e = 0; e < NEXP; e++)
        #pragma unroll
        for (int off = 16; off > 0; off >>= 1)
            acc[e] += __shfl_xor_sync(0xFFFFFFFFu, acc[e], off);

    int i0 = 0; float v0 = acc[0];
    #pragma unroll
    for (int e = 1; e < NEXP; e++) if (acc[e] > v0) { v0 = acc[e]; i0 = e; }
    int i1 = -1; float v1 = -3.4e38f;
    #pragma unroll
    for (int e = 0; e < NEXP; e++) if (e != i0 && acc[e] > v1) { v1 = acc[e]; i1 = e; }

    const float ex = expf(v1 - v0);
    const float w0 = 1.f / (1.f + ex);
    const float w1 = ex / (1.f + ex);
    // SCALING = 1.0 folded

    if (lane < NEXP)
        g_wfull[(size_t)tok * NEXP + lane] =
            (lane == i0) ? w0 : (lane == i1) ? w1 : 0.f;
}

// ---------------------------------------------------------------------------
// Split-K reduce of g_si + expert-weight mask -> fp16 g_sih.
// One thread per 4 columns (all 4 share one expert since 4 | 16).
// ---------------------------------------------------------------------------
__global__ void mask_reduce_kernel()
{
    const int idx  = blockIdx.x * blockDim.x + threadIdx.x;  // 0 .. BT*32-1
    const int tok  = idx >> 5;
    const int c4   = (idx & 31) * 4;
    const float f  = g_wfull[(size_t)tok * NEXP + (c4 >> 4)];

    const size_t off = (size_t)tok * ERC + c4;
    float4 s = *(const float4*)(g_si + off);
    #pragma unroll
    for (int p = 1; p < KSPLIT; p++) {
        float4 q = *(const float4*)(g_si + (size_t)p * BT * ERC + off);
        s.x += q.x; s.y += q.y; s.z += q.z; s.w += q.w;
    }
    __half2 hh[2];
    hh[0] = __float22half2_rn(make_float2(s.x * f, s.y * f));
    hh[1] = __float22half2_rn(make_float2(s.z * f, s.w * f));
    *(uint2*)(g_sih + off) = *(const uint2*)hh;
}

// ---------------------------------------------------------------------------
// f32 -> f16 conversion (round-to-nearest), 8 elements per thread
// ---------------------------------------------------------------------------
__global__ void f2h_kernel(const float* __restrict__ in, __half* __restrict__ out)
{
    const size_t i = ((size_t)blockIdx.x * blockDim.x + threadIdx.x) * 8;
    float4 v0 = *(const float4*)(in + i);
    float4 v1 = *(const float4*)(in + i + 4);
    __half2 h[4];
    h[0] = __float22half2_rn(make_float2(v0.x, v0.y));
    h[1] = __float22half2_rn(make_float2(v0.z, v0.w));
    h[2] = __float22half2_rn(make_float2(v1.x, v1.y));
    h[3] = __float22half2_rn(make_float2(v1.z, v1.w));
    *(uint4*)(out + i) = *(uint4*)h;
}

// ---------------------------------------------------------------------------
// Repack B_w [E][O][R] -> g_ballh [O][E*R] (fp16)
// ---------------------------------------------------------------------------
__global__ void prep_ball_kernel(const float* __restrict__ Bw)
{
    int idx = blockIdx.x * blockDim.x + threadIdx.x;
    int o = idx >> 7;
    int c = idx & 127;
    g_ballh[idx] = __float2half_rn(
        Bw[(size_t)(c >> 4) * OUT_F * RLOR + (size_t)o * RLOR + (c & 15)]);
}

// ---------------------------------------------------------------------------
extern "C" void kernel_launch(void* const* d_in, const int* in_sizes, int n_in,
                              void* d_out, int out_size)
{
    const float* x  = (const float*)d_in[0];   // [B,T,IN]
    const float* Wb = (const float*)d_in[1];   // [OUT,IN]
    const float* bb = (const float*)d_in[2];   // [OUT]
    const float* Wr = (const float*)d_in[3];   // [E,IN]
    const float* Aw = (const float*)d_in[4];   // [E,R,IN] == A_all [ERC][IN]
    const float* Bw = (const float*)d_in[5];   // [E,OUT,R]
    float* out = (float*)d_out;

    __half *xh, *wbh, *awh, *sih, *ballh;
    float* si;
    cudaGetSymbolAddress((void**)&xh,    g_xh);
    cudaGetSymbolAddress((void**)&wbh,   g_wbh);
    cudaGetSymbolAddress((void**)&awh,   g_awh);
    cudaGetSymbolAddress((void**)&si,    g_si);
    cudaGetSymbolAddress((void**)&sih,   g_sih);
    cudaGetSymbolAddress((void**)&ballh, g_ballh);

    cudaFuncSetAttribute(gemm_f16_kernel,
                         cudaFuncAttributeMaxDynamicSharedMemorySize, SMEM_BYTES);

    // 0) fused router + x fp16 conversion (single pass over fp32 x)
    router_conv_kernel<<<BT / 8, 256>>>(x, Wr);

    // 0b) remaining conversions
    f2h_kernel<<<(size_t)OUT_F * IN_F / 2048, 256>>>(Wb, wbh);
    f2h_kernel<<<(size_t)ERC * IN_F / 2048, 256>>>(Aw, awh);
    prep_ball_kernel<<<(OUT_F * ERC) / 256, 256>>>(Bw);

    // 1) si partials = x @ A_all^T   (M=8192, N=128, K=4096, split-K x4)
    dim3 g1(ERC / BN, BT / BM, KSPLIT);
    gemm_f16_kernel<<<g1, 256, SMEM_BYTES>>>(
        xh, IN_F, awh, IN_F, IN_F / KSPLIT,
        nullptr, 0, nullptr, 0, 0,
        si, ERC, nullptr, (size_t)BT * ERC);

    // 2) split-K reduce + expert mask -> fp16 si
    mask_reduce_kernel<<<BT * 32 / 256, 256>>>();

    // 3) out = x @ W_base^T (K=4096) + si @ B_all^T (K=128) + b
    dim3 g2(OUT_F / BN, BT / BM, 1);
    gemm_f16_kernel<<<g2, 256, SMEM_BYTES>>>(
        xh, IN_F, wbh, IN_F, IN_F,
        sih, ERC, ballh, ERC, ERC,
        out, OUT_F, bb, 0);
}

// round 14
// speedup vs baseline: 1.0002x; 1.0002x over previous
#include <cuda_runtime.h>
#include <cuda_fp16.h>
#include <cstdint>
#include <cstddef>

// Problem shape (fixed by the dataset)
#define BT   8192
#define IN_F 4096
#define OUT_F 4096
#define NEXP 8
#define RLOR 16
#define ERC  128
#define KSPLIT 4

// GEMM tiling (fp16 operands, fp32 accum) — R7 champion config
#define BM 128
#define BN 128
#define BKT 64                        // K halves per chunk = 128B rows
#define NSTAGE 3
#define PADH 72                       // smem row stride in halves (144B)
#define TILE_B (BM * PADH * 2)        // 18432 B per tile
#define STAGE_B (2 * TILE_B)          // 36864 B per stage
#define SMEM_BYTES (NSTAGE * STAGE_B) // 110592 B

// Scratch (no device allocation allowed -> __device__ globals)
__device__ __half g_xh [(size_t)BT * IN_F];         // 64 MB: x in fp16
__device__ __half g_wbh[(size_t)OUT_F * IN_F];      // 32 MB: W_base in fp16
__device__ __half g_awh[(size_t)ERC * IN_F];        // 1 MB:  A_all in fp16
__device__ __half g_ballh[(size_t)OUT_F * ERC];     // 1 MB:  B_all repacked fp16
__device__ float  g_si [(size_t)KSPLIT * BT * ERC]; // 16 MB: split-K fp32 partials
__device__ __half g_sih[(size_t)BT * ERC];          // 2 MB:  scaled si in fp16
__device__ float  g_wfull[(size_t)BT * NEXP];       // 256 KB: per-token expert weights

__device__ __forceinline__ uint32_t smem_u32(const void* p) {
    uint32_t a;
    asm("{ .reg .u64 t; cvta.to.shared.u64 t, %1; cvt.u32.u64 %0, t; }" : "=r"(a) : "l"(p));
    return a;
}
__device__ __forceinline__ void cpa16(uint32_t dst, const void* src) {
    asm volatile("cp.async.cg.shared.global [%0], [%1], 16;" :: "r"(dst), "l"(src));
}
#define CPA_COMMIT() asm volatile("cp.async.commit_group;" ::: "memory")
#define CPA_WAIT(n)  asm volatile("cp.async.wait_group %0;" :: "n"(n) : "memory")

__device__ __forceinline__ void ldsm_x4(uint32_t& r0, uint32_t& r1,
                                        uint32_t& r2, uint32_t& r3, uint32_t addr) {
    asm volatile("ldmatrix.sync.aligned.m8n8.x4.shared.b16 {%0,%1,%2,%3}, [%4];"
                 : "=r"(r0), "=r"(r1), "=r"(r2), "=r"(r3) : "r"(addr));
}

__device__ __forceinline__ void mma_f16(float c[4],
                                        uint32_t a0, uint32_t a1, uint32_t a2, uint32_t a3,
                                        uint32_t b0, uint32_t b1) {
    asm volatile(
        "mma.sync.aligned.m16n8k16.row.col.f32.f16.f16.f32 "
        "{%0,%1,%2,%3}, {%4,%5,%6,%7}, {%8,%9}, {%0,%1,%2,%3};"
        : "+f"(c[0]), "+f"(c[1]), "+f"(c[2]), "+f"(c[3])
        : "r"(a0), "r"(a1), "r"(a2), "r"(a3), "r"(b0), "r"(b1));
}

// ---------------------------------------------------------------------------
// Dual-phase FP16 GEMM (cp.async 3-stage, ldmatrix fragments) — R7 config.
//   C = A0 @ B0^T (K0) + A1 @ B1^T (K1) + bias   (fp32 accumulate/output)
// A row-major [M][lda], B row-major [N][ldb], lda/ldb in halves.
// blockIdx.z = split-K slice (offsets A0/B0 by z*K0 along K, C by z*cpart).
// ---------------------------------------------------------------------------
__global__ __launch_bounds__(256, 2)
void gemm_f16_kernel(const __half* __restrict__ A0, int lda0,
                     const __half* __restrict__ B0, int ldb0, int K0,
                     const __half* __restrict__ A1, int lda1,
                     const __half* __restrict__ B1, int ldb1, int K1,
                     float* __restrict__ C, int ldc,
                     const float* __restrict__ bias,
                     size_t cpart)
{
    extern __shared__ char smem_raw[];

    const int z = blockIdx.z;
    A0 += (size_t)z * K0;
    B0 += (size_t)z * K0;
    C  += (size_t)z * cpart;

    const int tid  = threadIdx.x;
    const int bm   = blockIdx.y * BM;
    const int bn   = blockIdx.x * BN;
    const int warp = tid >> 5;
    const int lane = tid & 31;
    const int wm   = (warp >> 2) * 64;   // 2 warps along M
    const int wn   = (warp & 3) * 32;    // 4 warps along N
    const int g    = lane >> 2;
    const int t4   = lane & 3;

    float acc[4][4][4];
    #pragma unroll
    for (int i = 0; i < 4; i++)
        #pragma unroll
        for (int j = 0; j < 4; j++)
            #pragma unroll
            for (int v = 0; v < 4; v++) acc[i][j][v] = 0.f;

    // Loader: 4 slabs of 32 rows; 8 threads x 16B (8 halves) across a 64-half row
    const int l_row  = tid >> 3;           // 0..31
    const int l_colh = (tid & 7) * 8;      // 0..56 halves

    const uint32_t smem_base = smem_u32(smem_raw);
    const uint32_t wA0 = smem_base + (l_row * PADH + l_colh) * 2;
    const uint32_t wB0 = wA0 + TILE_B;

    // ldmatrix per-thread row/col selectors
    const int lm_a_row = lane & 15;
    const int lm_a_k8  = (lane >> 4) * 8;
    const int lm_b_row = ((lane >> 4) & 1) * 8 + (lane & 7);
    const int lm_b_k8  = ((lane >> 3) & 1) * 8;

    const int T0 = K0 / BKT;
    const int T1 = K1 / BKT;
    const int T  = T0 + T1;

    auto load_chunk = [&](int c) {
        const uint32_t st = (uint32_t)(c % NSTAGE) * STAGE_B;
        const __half *A, *B; int lda, ldb, k0;
        if (c < T0) { A = A0; lda = lda0; B = B0; ldb = ldb0; k0 = c * BKT; }
        else        { A = A1; lda = lda1; B = B1; ldb = ldb1; k0 = (c - T0) * BKT; }
        const __half* ap = A + (size_t)(bm + l_row) * lda + k0 + l_colh;
        const __half* bp = B + (size_t)(bn + l_row) * ldb + k0 + l_colh;
        #pragma unroll
        for (int i = 0; i < 4; i++) {
            cpa16(st + wA0 + i * (32 * PADH * 2), ap + (size_t)(i * 32) * lda);
            cpa16(st + wB0 + i * (32 * PADH * 2), bp + (size_t)(i * 32) * ldb);
        }
    };

    auto compute = [&](int buf) {
        const uint32_t aB = smem_base + (uint32_t)buf * STAGE_B;
        const uint32_t bB = aB + TILE_B;
        #pragma unroll
        for (int ks = 0; ks < 4; ks++) {          // each ks = one k16 step
            const int kh = ks * 16;                // half offset
            uint32_t af[4][4], bf[4][2];
            #pragma unroll
            for (int mt = 0; mt < 4; mt++) {
                const uint32_t ad = aB +
                    ((wm + mt * 16 + lm_a_row) * PADH + kh + lm_a_k8) * 2;
                ldsm_x4(af[mt][0], af[mt][1], af[mt][2], af[mt][3], ad);
            }
            #pragma unroll
            for (int pr = 0; pr < 2; pr++) {
                const uint32_t bd = bB +
                    ((wn + pr * 16 + lm_b_row) * PADH + kh + lm_b_k8) * 2;
                ldsm_x4(bf[2 * pr][0], bf[2 * pr][1],
                        bf[2 * pr + 1][0], bf[2 * pr + 1][1], bd);
            }
            #pragma unroll
            for (int mt = 0; mt < 4; mt++)
                #pragma unroll
                for (int nt = 0; nt < 4; nt++)
                    mma_f16(acc[mt][nt], af[mt][0], af[mt][1], af[mt][2], af[mt][3],
                            bf[nt][0], bf[nt][1]);
        }
    };

    // prologue: stages 0..NSTAGE-2
    #pragma unroll
    for (int p = 0; p < NSTAGE - 1; p++) {
        if (p < T) load_chunk(p);
        CPA_COMMIT();
    }

    for (int t = 0; t < T; t++) {
        CPA_WAIT(NSTAGE - 2);       // chunk t landed
        __syncthreads();            // visibility + stage reuse guard
        if (t + NSTAGE - 1 < T) load_chunk(t + NSTAGE - 1);
        CPA_COMMIT();
        compute(t % NSTAGE);
    }

    // Epilogue (fp32)
    #pragma unroll
    for (int mt = 0; mt < 4; mt++) {
        #pragma unroll
        for (int nt = 0; nt < 4; nt++) {
            const int row0 = bm + wm + mt * 16 + g;
            const int col0 = bn + wn + nt * 8 + t4 * 2;
            float bv0 = 0.f, bv1 = 0.f;
            if (bias) { bv0 = bias[col0]; bv1 = bias[col0 + 1]; }
            float2 o0 = make_float2(acc[mt][nt][0] + bv0, acc[mt][nt][1] + bv1);
            float2 o1 = make_float2(acc[mt][nt][2] + bv0, acc[mt][nt][3] + bv1);
            *(float2*)(C + (size_t)row0 * ldc + col0)       = o0;
            *(float2*)(C + (size_t)(row0 + 8) * ldc + col0) = o1;
        }
    }
}

// ---------------------------------------------------------------------------
// Fused router + x conversion. One warp per token:
//  - single pass over fp32 x row: accumulate 8 router dots (exact fp32)
//    AND write the fp16 row of g_xh.
//  - top-2 + softmax -> dense per-token expert weight vector g_wfull[tok][e].
// ---------------------------------------------------------------------------
__global__ void router_conv_kernel(const float* __restrict__ x,
                                   const float* __restrict__ Wr)
{
    const int tok  = (blockIdx.x * blockDim.x + threadIdx.x) >> 5;
    const int lane = threadIdx.x & 31;
    if (tok >= BT) return;

    const float* xr = x + (size_t)tok * IN_F;
    __half* xo = g_xh + (size_t)tok * IN_F;
    float acc[NEXP];
    #pragma unroll
    for (int e = 0; e < NEXP; e++) acc[e] = 0.f;

    for (int k = lane * 4; k < IN_F; k += 128) {
        float4 xv = *(const float4*)(xr + k);
        // fused fp16 conversion write (8B per lane)
        __half2 hh[2];
        hh[0] = __float22half2_rn(make_float2(xv.x, xv.y));
        hh[1] = __float22half2_rn(make_float2(xv.z, xv.w));
        *(uint2*)(xo + k) = *(const uint2*)hh;
        #pragma unroll
        for (int e = 0; e < NEXP; e++) {
            float4 wv = *(const float4*)(Wr + (size_t)e * IN_F + k);
            acc[e] += xv.x * wv.x + xv.y * wv.y + xv.z * wv.z + xv.w * wv.w;
        }
    }
    #pragma unroll
    for (int e = 0; e < NEXP; e++)
        #pragma unroll
        for (int off = 16; off > 0; off >>= 1)
            acc[e] += __shfl_xor_sync(0xFFFFFFFFu, acc[e], off);

    int i0 = 0; float v0 = acc[0];
    #pragma unroll
    for (int e = 1; e < NEXP; e++) if (acc[e] > v0) { v0 = acc[e]; i0 = e; }
    int i1 = -1; float v1 = -3.4e38f;
    #pragma unroll
    for (int e = 0; e < NEXP; e++) if (e != i0 && acc[e] > v1) { v1 = acc[e]; i1 = e; }

    const float ex = expf(v1 - v0);
    const float w0 = 1.f / (1.f + ex);
    const float w1 = ex / (1.f + ex);
    // SCALING = 1.0 folded

    if (lane < NEXP)
        g_wfull[(size_t)tok * NEXP + lane] =
            (lane == i0) ? w0 : (lane == i1) ? w1 : 0.f;
}

// ---------------------------------------------------------------------------
// Split-K reduce of g_si + expert-weight mask -> fp16 g_sih.
// One thread per 4 columns (all 4 share one expert since 4 | 16).
// ---------------------------------------------------------------------------
__global__ void mask_reduce_kernel()
{
    const int idx  = blockIdx.x * blockDim.x + threadIdx.x;  // 0 .. BT*32-1
    const int tok  = idx >> 5;
    const int c4   = (idx & 31) * 4;
    const float f  = g_wfull[(size_t)tok * NEXP + (c4 >> 4)];

    const size_t off = (size_t)tok * ERC + c4;
    float4 s = *(const float4*)(g_si + off);
    #pragma unroll
    for (int p = 1; p < KSPLIT; p++) {
        float4 q = *(const float4*)(g_si + (size_t)p * BT * ERC + off);
        s.x += q.x; s.y += q.y; s.z += q.z; s.w += q.w;
    }
    __half2 hh[2];
    hh[0] = __float22half2_rn(make_float2(s.x * f, s.y * f));
    hh[1] = __float22half2_rn(make_float2(s.z * f, s.w * f));
    *(uint2*)(g_sih + off) = *(const uint2*)hh;
}

// ---------------------------------------------------------------------------
// f32 -> f16 conversion (round-to-nearest), 8 elements per thread
// ---------------------------------------------------------------------------
__global__ void f2h_kernel(const float* __restrict__ in, __half* __restrict__ out)
{
    const size_t i = ((size_t)blockIdx.x * blockDim.x + threadIdx.x) * 8;
    float4 v0 = *(const float4*)(in + i);
    float4 v1 = *(const float4*)(in + i + 4);
    __half2 h[4];
    h[0] = __float22half2_rn(make_float2(v0.x, v0.y));
    h[1] = __float22half2_rn(make_float2(v0.z, v0.w));
    h[2] = __float22half2_rn(make_float2(v1.x, v1.y));
    h[3] = __float22half2_rn(make_float2(v1.z, v1.w));
    *(uint4*)(out + i) = *(uint4*)h;
}

// ---------------------------------------------------------------------------
// Repack B_w [E][O][R] -> g_ballh [O][E*R] (fp16)
// ---------------------------------------------------------------------------
__global__ void prep_ball_kernel(const float* __restrict__ Bw)
{
    int idx = blockIdx.x * blockDim.x + threadIdx.x;
    int o = idx >> 7;
    int c = idx & 127;
    g_ballh[idx] = __float2half_rn(
        Bw[(size_t)(c >> 4) * OUT_F * RLOR + (size_t)o * RLOR + (c & 15)]);
}

// ---------------------------------------------------------------------------
extern "C" void kernel_launch(void* const* d_in, const int* in_sizes, int n_in,
                              void* d_out, int out_size)
{
    const float* x  = (const float*)d_in[0];   // [B,T,IN]
    const float* Wb = (const float*)d_in[1];   // [OUT,IN]
    const float* bb = (const float*)d_in[2];   // [OUT]
    const float* Wr = (const float*)d_in[3];   // [E,IN]
    const float* Aw = (const float*)d_in[4];   // [E,R,IN] == A_all [ERC][IN]
    const float* Bw = (const float*)d_in[5];   // [E,OUT,R]
    float* out = (float*)d_out;

    __half *xh, *wbh, *awh, *sih, *ballh;
    float* si;
    cudaGetSymbolAddress((void**)&xh,    g_xh);
    cudaGetSymbolAddress((void**)&wbh,   g_wbh);
    cudaGetSymbolAddress((void**)&awh,   g_awh);
    cudaGetSymbolAddress((void**)&si,    g_si);
    cudaGetSymbolAddress((void**)&sih,   g_sih);
    cudaGetSymbolAddress((void**)&ballh, g_ballh);

    cudaFuncSetAttribute(gemm_f16_kernel,
                         cudaFuncAttributeMaxDynamicSharedMemorySize, SMEM_BYTES);

    // 0) fused router + x fp16 conversion (single pass over fp32 x)
    router_conv_kernel<<<BT / 8, 256>>>(x, Wr);

    // 0b) remaining conversions
    f2h_kernel<<<(size_t)OUT_F * IN_F / 2048, 256>>>(Wb, wbh);
    f2h_kernel<<<(size_t)ERC * IN_F / 2048, 256>>>(Aw, awh);
    prep_ball_kernel<<<(OUT_F * ERC) / 256, 256>>>(Bw);

    // 1) si partials = x @ A_all^T   (M=8192, N=128, K=4096, split-K x4)
    dim3 g1(ERC / BN, BT / BM, KSPLIT);
    gemm_f16_kernel<<<g1, 256, SMEM_BYTES>>>(
        xh, IN_F, awh, IN_F, IN_F / KSPLIT,
        nullptr, 0, nullptr, 0, 0,
        si, ERC, nullptr, (size_t)BT * ERC);

    // 2) split-K reduce + expert mask -> fp16 si
    mask_reduce_kernel<<<BT * 32 / 256, 256>>>();

    // 3) out = x @ W_base^T (K=4096) + si @ B_all^T (K=128) + b
    dim3 g2(OUT_F / BN, BT / BM, 1);
    gemm_f16_kernel<<<g2, 256, SMEM_BYTES>>>(
        xh, IN_F, wbh, IN_F, IN_F,
        sih, ERC, ballh, ERC, ERC,
        out, OUT_F, bb, 0);
}

// round 15
// speedup vs baseline: 1.0023x; 1.0020x over previous
#include <cuda_runtime.h>
#include <cuda_fp16.h>
#include <cstdint>
#include <cstddef>

// Problem shape (fixed by the dataset)
#define BT   8192
#define IN_F 4096
#define OUT_F 4096
#define NEXP 8
#define RLOR 16
#define ERC  128
#define KSPLIT 4

// GEMM tiling (fp16 operands, fp32 accum) — R7 champion config
#define BM 128
#define BN 128
#define BKT 64                        // K halves per chunk = 128B rows
#define NSTAGE 3
#define PADH 72                       // smem row stride in halves (144B)
#define TILE_B (BM * PADH * 2)        // 18432 B per tile
#define STAGE_B (2 * TILE_B)          // 36864 B per stage
#define SMEM_BYTES (NSTAGE * STAGE_B) // 110592 B

// Scratch (no device allocation allowed -> __device__ globals)
__device__ __half g_xh [(size_t)BT * IN_F];         // 64 MB: x in fp16
__device__ __half g_wbh[(size_t)OUT_F * IN_F];      // 32 MB: W_base in fp16
__device__ __half g_awh[(size_t)ERC * IN_F];        // 1 MB:  A_all in fp16
__device__ __half g_ballh[(size_t)OUT_F * ERC];     // 1 MB:  B_all repacked fp16
__device__ float  g_si [(size_t)KSPLIT * BT * ERC]; // 16 MB: split-K fp32 partials
__device__ __half g_sih[(size_t)BT * ERC];          // 2 MB:  scaled si in fp16
__device__ float  g_wfull[(size_t)BT * NEXP];       // 256 KB: per-token expert weights

__device__ __forceinline__ uint32_t smem_u32(const void* p) {
    uint32_t a;
    asm("{ .reg .u64 t; cvta.to.shared.u64 t, %1; cvt.u32.u64 %0, t; }" : "=r"(a) : "l"(p));
    return a;
}
__device__ __forceinline__ void cpa16(uint32_t dst, const void* src) {
    asm volatile("cp.async.cg.shared.global [%0], [%1], 16;" :: "r"(dst), "l"(src));
}
#define CPA_COMMIT() asm volatile("cp.async.commit_group;" ::: "memory")
#define CPA_WAIT(n)  asm volatile("cp.async.wait_group %0;" :: "n"(n) : "memory")

__device__ __forceinline__ void ldsm_x4(uint32_t& r0, uint32_t& r1,
                                        uint32_t& r2, uint32_t& r3, uint32_t addr) {
    asm volatile("ldmatrix.sync.aligned.m8n8.x4.shared.b16 {%0,%1,%2,%3}, [%4];"
                 : "=r"(r0), "=r"(r1), "=r"(r2), "=r"(r3) : "r"(addr));
}

__device__ __forceinline__ void mma_f16(float c[4],
                                        uint32_t a0, uint32_t a1, uint32_t a2, uint32_t a3,
                                        uint32_t b0, uint32_t b1) {
    asm volatile(
        "mma.sync.aligned.m16n8k16.row.col.f32.f16.f16.f32 "
        "{%0,%1,%2,%3}, {%4,%5,%6,%7}, {%8,%9}, {%0,%1,%2,%3};"
        : "+f"(c[0]), "+f"(c[1]), "+f"(c[2]), "+f"(c[3])
        : "r"(a0), "r"(a1), "r"(a2), "r"(a3), "r"(b0), "r"(b1));
}

// ---------------------------------------------------------------------------
// Dual-phase FP16 GEMM (cp.async 3-stage, ldmatrix fragments) — R7 config.
//   C = A0 @ B0^T (K0) + A1 @ B1^T (K1) + bias   (fp32 accumulate/output)
// A row-major [M][lda], B row-major [N][ldb], lda/ldb in halves.
// blockIdx.z = split-K slice (offsets A0/B0 by z*K0 along K, C by z*cpart).
// ---------------------------------------------------------------------------
__global__ __launch_bounds__(256, 2)
void gemm_f16_kernel(const __half* __restrict__ A0, int lda0,
                     const __half* __restrict__ B0, int ldb0, int K0,
                     const __half* __restrict__ A1, int lda1,
                     const __half* __restrict__ B1, int ldb1, int K1,
                     float* __restrict__ C, int ldc,
                     const float* __restrict__ bias,
                     size_t cpart)
{
    extern __shared__ char smem_raw[];

    const int z = blockIdx.z;
    A0 += (size_t)z * K0;
    B0 += (size_t)z * K0;
    C  += (size_t)z * cpart;

    const int tid  = threadIdx.x;
    const int bm   = blockIdx.y * BM;
    const int bn   = blockIdx.x * BN;
    const int warp = tid >> 5;
    const int lane = tid & 31;
    const int wm   = (warp >> 2) * 64;   // 2 warps along M
    const int wn   = (warp & 3) * 32;    // 4 warps along N
    const int g    = lane >> 2;
    const int t4   = lane & 3;

    float acc[4][4][4];
    #pragma unroll
    for (int i = 0; i < 4; i++)
        #pragma unroll
        for (int j = 0; j < 4; j++)
            #pragma unroll
            for (int v = 0; v < 4; v++) acc[i][j][v] = 0.f;

    // Loader: 4 slabs of 32 rows; 8 threads x 16B (8 halves) across a 64-half row
    const int l_row  = tid >> 3;           // 0..31
    const int l_colh = (tid & 7) * 8;      // 0..56 halves

    const uint32_t smem_base = smem_u32(smem_raw);
    const uint32_t wA0 = smem_base + (l_row * PADH + l_colh) * 2;
    const uint32_t wB0 = wA0 + TILE_B;

    // ldmatrix per-thread row/col selectors
    const int lm_a_row = lane & 15;
    const int lm_a_k8  = (lane >> 4) * 8;
    const int lm_b_row = ((lane >> 4) & 1) * 8 + (lane & 7);
    const int lm_b_k8  = ((lane >> 3) & 1) * 8;

    const int T0 = K0 / BKT;
    const int T1 = K1 / BKT;
    const int T  = T0 + T1;

    auto load_chunk = [&](int c) {
        const uint32_t st = (uint32_t)(c % NSTAGE) * STAGE_B;
        const __half *A, *B; int lda, ldb, k0;
        if (c < T0) { A = A0; lda = lda0; B = B0; ldb = ldb0; k0 = c * BKT; }
        else        { A = A1; lda = lda1; B = B1; ldb = ldb1; k0 = (c - T0) * BKT; }
        const __half* ap = A + (size_t)(bm + l_row) * lda + k0 + l_colh;
        const __half* bp = B + (size_t)(bn + l_row) * ldb + k0 + l_colh;
        #pragma unroll
        for (int i = 0; i < 4; i++) {
            cpa16(st + wA0 + i * (32 * PADH * 2), ap + (size_t)(i * 32) * lda);
            cpa16(st + wB0 + i * (32 * PADH * 2), bp + (size_t)(i * 32) * ldb);
        }
    };

    auto compute = [&](int buf) {
        const uint32_t aB = smem_base + (uint32_t)buf * STAGE_B;
        const uint32_t bB = aB + TILE_B;
        #pragma unroll
        for (int ks = 0; ks < 4; ks++) {          // each ks = one k16 step
            const int kh = ks * 16;                // half offset
            uint32_t af[4][4], bf[4][2];
            #pragma unroll
            for (int mt = 0; mt < 4; mt++) {
                const uint32_t ad = aB +
                    ((wm + mt * 16 + lm_a_row) * PADH + kh + lm_a_k8) * 2;
                ldsm_x4(af[mt][0], af[mt][1], af[mt][2], af[mt][3], ad);
            }
            #pragma unroll
            for (int pr = 0; pr < 2; pr++) {
                const uint32_t bd = bB +
                    ((wn + pr * 16 + lm_b_row) * PADH + kh + lm_b_k8) * 2;
                ldsm_x4(bf[2 * pr][0], bf[2 * pr][1],
                        bf[2 * pr + 1][0], bf[2 * pr + 1][1], bd);
            }
            #pragma unroll
            for (int mt = 0; mt < 4; mt++)
                #pragma unroll
                for (int nt = 0; nt < 4; nt++)
                    mma_f16(acc[mt][nt], af[mt][0], af[mt][1], af[mt][2], af[mt][3],
                            bf[nt][0], bf[nt][1]);
        }
    };

    // prologue: stages 0..NSTAGE-2
    #pragma unroll
    for (int p = 0; p < NSTAGE - 1; p++) {
        if (p < T) load_chunk(p);
        CPA_COMMIT();
    }

    for (int t = 0; t < T; t++) {
        CPA_WAIT(NSTAGE - 2);       // chunk t landed
        __syncthreads();            // visibility + stage reuse guard
        if (t + NSTAGE - 1 < T) load_chunk(t + NSTAGE - 1);
        CPA_COMMIT();
        compute(t % NSTAGE);
    }

    // Epilogue (fp32)
    #pragma unroll
    for (int mt = 0; mt < 4; mt++) {
        #pragma unroll
        for (int nt = 0; nt < 4; nt++) {
            const int row0 = bm + wm + mt * 16 + g;
            const int col0 = bn + wn + nt * 8 + t4 * 2;
            float bv0 = 0.f, bv1 = 0.f;
            if (bias) { bv0 = bias[col0]; bv1 = bias[col0 + 1]; }
            float2 o0 = make_float2(acc[mt][nt][0] + bv0, acc[mt][nt][1] + bv1);
            float2 o1 = make_float2(acc[mt][nt][2] + bv0, acc[mt][nt][3] + bv1);
            *(float2*)(C + (size_t)row0 * ldc + col0)       = o0;
            *(float2*)(C + (size_t)(row0 + 8) * ldc + col0) = o1;
        }
    }
}

// ---------------------------------------------------------------------------
// Fused router + x conversion. One warp per token:
//  - single pass over fp32 x row: accumulate 8 router dots (exact fp32)
//    AND write the fp16 row of g_xh.
//  - top-2 + softmax -> dense per-token expert weight vector g_wfull[tok][e].
// ---------------------------------------------------------------------------
__global__ void router_conv_kernel(const float* __restrict__ x,
                                   const float* __restrict__ Wr)
{
    const int tok  = (blockIdx.x * blockDim.x + threadIdx.x) >> 5;
    const int lane = threadIdx.x & 31;
    if (tok >= BT) return;

    const float* xr = x + (size_t)tok * IN_F;
    __half* xo = g_xh + (size_t)tok * IN_F;
    float acc[NEXP];
    #pragma unroll
    for (int e = 0; e < NEXP; e++) acc[e] = 0.f;

    for (int k = lane * 4; k < IN_F; k += 128) {
        float4 xv = *(const float4*)(xr + k);
        // fused fp16 conversion write (8B per lane)
        __half2 hh[2];
        hh[0] = __float22half2_rn(make_float2(xv.x, xv.y));
        hh[1] = __float22half2_rn(make_float2(xv.z, xv.w));
        *(uint2*)(xo + k) = *(const uint2*)hh;
        #pragma unroll
        for (int e = 0; e < NEXP; e++) {
            float4 wv = *(const float4*)(Wr + (size_t)e * IN_F + k);
            acc[e] += xv.x * wv.x + xv.y * wv.y + xv.z * wv.z + xv.w * wv.w;
        }
    }
    #pragma unroll
    for (int e = 0; e < NEXP; e++)
        #pragma unroll
        for (int off = 16; off > 0; off >>= 1)
            acc[e] += __shfl_xor_sync(0xFFFFFFFFu, acc[e], off);

    int i0 = 0; float v0 = acc[0];
    #pragma unroll
    for (int e = 1; e < NEXP; e++) if (acc[e] > v0) { v0 = acc[e]; i0 = e; }
    int i1 = -1; float v1 = -3.4e38f;
    #pragma unroll
    for (int e = 0; e < NEXP; e++) if (e != i0 && acc[e] > v1) { v1 = acc[e]; i1 = e; }

    const float ex = expf(v1 - v0);
    const float w0 = 1.f / (1.f + ex);
    const float w1 = ex / (1.f + ex);
    // SCALING = 1.0 folded

    if (lane < NEXP)
        g_wfull[(size_t)tok * NEXP + lane] =
            (lane == i0) ? w0 : (lane == i1) ? w1 : 0.f;
}

// ---------------------------------------------------------------------------
// Split-K reduce of g_si + expert-weight mask -> fp16 g_sih.
// One thread per 4 columns (all 4 share one expert since 4 | 16).
// ---------------------------------------------------------------------------
__global__ void mask_reduce_kernel()
{
    const int idx  = blockIdx.x * blockDim.x + threadIdx.x;  // 0 .. BT*32-1
    const int tok  = idx >> 5;
    const int c4   = (idx & 31) * 4;
    const float f  = g_wfull[(size_t)tok * NEXP + (c4 >> 4)];

    const size_t off = (size_t)tok * ERC + c4;
    float4 s = *(const float4*)(g_si + off);
    #pragma unroll
    for (int p = 1; p < KSPLIT; p++) {
        float4 q = *(const float4*)(g_si + (size_t)p * BT * ERC + off);
        s.x += q.x; s.y += q.y; s.z += q.z; s.w += q.w;
    }
    __half2 hh[2];
    hh[0] = __float22half2_rn(make_float2(s.x * f, s.y * f));
    hh[1] = __float22half2_rn(make_float2(s.z * f, s.w * f));
    *(uint2*)(g_sih + off) = *(const uint2*)hh;
}

// ---------------------------------------------------------------------------
// f32 -> f16 conversion (round-to-nearest), 8 elements per thread
// ---------------------------------------------------------------------------
__global__ void f2h_kernel(const float* __restrict__ in, __half* __restrict__ out)
{
    const size_t i = ((size_t)blockIdx.x * blockDim.x + threadIdx.x) * 8;
    float4 v0 = *(const float4*)(in + i);
    float4 v1 = *(const float4*)(in + i + 4);
    __half2 h[4];
    h[0] = __float22half2_rn(make_float2(v0.x, v0.y));
    h[1] = __float22half2_rn(make_float2(v0.z, v0.w));
    h[2] = __float22half2_rn(make_float2(v1.x, v1.y));
    h[3] = __float22half2_rn(make_float2(v1.z, v1.w));
    *(uint4*)(out + i) = *(uint4*)h;
}

// ---------------------------------------------------------------------------
// Repack B_w [E][O][R] -> g_ballh [O][E*R] (fp16)
// ---------------------------------------------------------------------------
__global__ void prep_ball_kernel(const float* __restrict__ Bw)
{
    int idx = blockIdx.x * blockDim.x + threadIdx.x;
    int o = idx >> 7;
    int c = idx & 127;
    g_ballh[idx] = __float2half_rn(
        Bw[(size_t)(c >> 4) * OUT_F * RLOR + (size_t)o * RLOR + (c & 15)]);
}

// ---------------------------------------------------------------------------
extern "C" void kernel_launch(void* const* d_in, const int* in_sizes, int n_in,
                              void* d_out, int out_size)
{
    const float* x  = (const float*)d_in[0];   // [B,T,IN]
    const float* Wb = (const float*)d_in[1];   // [OUT,IN]
    const float* bb = (const float*)d_in[2];   // [OUT]
    const float* Wr = (const float*)d_in[3];   // [E,IN]
    const float* Aw = (const float*)d_in[4];   // [E,R,IN] == A_all [ERC][IN]
    const float* Bw = (const float*)d_in[5];   // [E,OUT,R]
    float* out = (float*)d_out;

    __half *xh, *wbh, *awh, *sih, *ballh;
    float* si;
    cudaGetSymbolAddress((void**)&xh,    g_xh);
    cudaGetSymbolAddress((void**)&wbh,   g_wbh);
    cudaGetSymbolAddress((void**)&awh,   g_awh);
    cudaGetSymbolAddress((void**)&si,    g_si);
    cudaGetSymbolAddress((void**)&sih,   g_sih);
    cudaGetSymbolAddress((void**)&ballh, g_ballh);

    cudaFuncSetAttribute(gemm_f16_kernel,
                         cudaFuncAttributeMaxDynamicSharedMemorySize, SMEM_BYTES);

    // 0) fused router + x fp16 conversion (single pass over fp32 x)
    router_conv_kernel<<<BT / 8, 256>>>(x, Wr);

    // 0b) remaining conversions
    f2h_kernel<<<(size_t)OUT_F * IN_F / 2048, 256>>>(Wb, wbh);
    f2h_kernel<<<(size_t)ERC * IN_F / 2048, 256>>>(Aw, awh);
    prep_ball_kernel<<<(OUT_F * ERC) / 256, 256>>>(Bw);

    // 1) si partials = x @ A_all^T   (M=8192, N=128, K=4096, split-K x4)
    dim3 g1(ERC / BN, BT / BM, KSPLIT);
    gemm_f16_kernel<<<g1, 256, SMEM_BYTES>>>(
        xh, IN_F, awh, IN_F, IN_F / KSPLIT,
        nullptr, 0, nullptr, 0, 0,
        si, ERC, nullptr, (size_t)BT * ERC);

    // 2) split-K reduce + expert mask -> fp16 si
    mask_reduce_kernel<<<BT * 32 / 256, 256>>>();

    // 3) out = x @ W_base^T (K=4096) + si @ B_all^T (K=128) + b
    dim3 g2(OUT_F / BN, BT / BM, 1);
    gemm_f16_kernel<<<g2, 256, SMEM_BYTES>>>(
        xh, IN_F, wbh, IN_F, IN_F,
        sih, ERC, ballh, ERC, ERC,
        out, OUT_F, bb, 0);
}